// round 1
// baseline (speedup 1.0000x reference)
#include <cuda_runtime.h>
#include <math.h>

#define BB 256
#define TT 1024
#define MM 64
#define KH 512
#define GATES 4

#define BC 64          // batch tile per CTA
#define HC 16          // hidden tile per CTA
#define GB (BB / BC)   // 4
#define GH (KH / HC)   // 32
#define NCTA (GB * GH) // 128
#define NTHREADS 256

#define WPAD 516       // 512 + 4 pad (bank-conflict mitigation)
#define XPAD 68        // 65 padded to multiple of 4
#define KCHUNK 128

// 512 MB hidden-state history scratch: hs[t][b][k]
__device__ float g_hs[(size_t)TT * BB * KH];
__device__ unsigned g_bar_count = 0;
__device__ unsigned g_bar_gen = 0;

__device__ __forceinline__ void grid_sync_all() {
    __syncthreads();
    if (threadIdx.x == 0) {
        __threadfence();
        unsigned gen = atomicAdd(&g_bar_gen, 0u);
        unsigned old = atomicInc(&g_bar_count, NCTA - 1); // wraps to 0 at NCTA-1
        if (old == NCTA - 1) {
            atomicAdd(&g_bar_gen, 1u);
        } else {
            while (atomicAdd(&g_bar_gen, 0u) == gen) {
                __nanosleep(64);
            }
        }
        __threadfence();
    }
    __syncthreads();
}

__device__ __forceinline__ float sigmoidf_(float x) {
    return 1.0f / (1.0f + expf(-x));
}

// ---------------------------------------------------------------------------
// Persistent LSTM recurrence kernel.
// Grid = 128 CTAs: CTA (bi, hj) owns batch rows [bi*64, +64) and hidden units
// [hj*16, +16). Per step: gates = x_t @ W_ih_sliceT + h_{t-1} @ W_hh_sliceT +
// bias; elementwise LSTM cell with c in registers; h_t written to g_hs; grid
// barrier.
// ---------------------------------------------------------------------------
__global__ void __launch_bounds__(NTHREADS, 1)
lstm_persistent(const float* __restrict__ inputs,   // [B, T, 65]
                const float* __restrict__ W_ih,     // [2048, 65]
                const float* __restrict__ W_hh,     // [2048, 512]
                const float* __restrict__ b_ih,     // [2048]
                const float* __restrict__ b_hh)     // [2048]
{
    extern __shared__ float smem[];
    float* sWhh  = smem;                          // [4][16][WPAD]
    float* sWih  = sWhh + GATES * HC * WPAD;      // [4][16][XPAD]
    float* sBias = sWih + GATES * HC * XPAD;      // [64]
    float* sX    = sBias + 64;                    // [64][XPAD]
    float* sH    = sX + BC * XPAD;                // [64][KCHUNK]

    const int cta = blockIdx.x;
    const int bi = cta / GH;
    const int hj = cta % GH;
    const int batch_base = bi * BC;
    const int hid_base = hj * HC;
    const int tid = threadIdx.x;
    const int tx = tid & 15;    // hidden unit within tile
    const int ty = tid >> 4;    // batch group (4 rows each)
    const int row0 = ty * 4;

    // ---- one-time loads into SMEM ----
    for (int idx = tid; idx < GATES * HC * 512; idx += NTHREADS) {
        int k = idx & 511;
        int row = idx >> 9;             // g*16 + hx
        int g = row >> 4, hx = row & 15;
        int grow = g * KH + hid_base + hx;
        sWhh[row * WPAD + k] = W_hh[(size_t)grow * KH + k];
    }
    for (int idx = tid; idx < GATES * HC * XPAD; idx += NTHREADS) {
        int j = idx % XPAD;
        int row = idx / XPAD;
        int g = row >> 4, hx = row & 15;
        int grow = g * KH + hid_base + hx;
        sWih[idx] = (j < 65) ? W_ih[(size_t)grow * 65 + j] : 0.0f;
    }
    for (int idx = tid; idx < GATES * HC; idx += NTHREADS) {
        int g = idx >> 4, hx = idx & 15;
        int grow = g * KH + hid_base + hx;
        sBias[idx] = b_ih[grow] + b_hh[grow];
    }
    for (int idx = tid; idx < BC; idx += NTHREADS) {
        sX[idx * XPAD + 65] = 0.0f;
        sX[idx * XPAD + 66] = 0.0f;
        sX[idx * XPAD + 67] = 0.0f;
    }
    __syncthreads();

    float c_reg[4] = {0.f, 0.f, 0.f, 0.f};

    for (int t = 0; t < TT; ++t) {
        // load x_t tile [64][65]
        for (int idx = tid; idx < BC * 65; idx += NTHREADS) {
            int r = idx / 65, j = idx - r * 65;
            sX[r * XPAD + j] =
                inputs[(size_t)(batch_base + r) * (TT * 65) + (size_t)t * 65 + j];
        }
        __syncthreads();

        float acc[4][4];
#pragma unroll
        for (int r = 0; r < 4; r++)
#pragma unroll
            for (int g = 0; g < 4; g++) acc[r][g] = sBias[g * HC + tx];

        // x contribution: K' = 68 (zero padded)
#pragma unroll 4
        for (int q = 0; q < XPAD / 4; q++) {
            float4 hv[4], wv[4];
#pragma unroll
            for (int r = 0; r < 4; r++)
                hv[r] = *(const float4*)&sX[(row0 + r) * XPAD + q * 4];
#pragma unroll
            for (int g = 0; g < 4; g++)
                wv[g] = *(const float4*)&sWih[(g * HC + tx) * XPAD + q * 4];
#pragma unroll
            for (int r = 0; r < 4; r++)
#pragma unroll
                for (int g = 0; g < 4; g++)
                    acc[r][g] += hv[r].x * wv[g].x + hv[r].y * wv[g].y +
                                 hv[r].z * wv[g].z + hv[r].w * wv[g].w;
        }

        // h contribution (h_{-1} == 0, so skip at t == 0)
        if (t > 0) {
            const float4* hsrc = (const float4*)(g_hs + (size_t)(t - 1) * BB * KH +
                                                 (size_t)batch_base * KH);
            for (int kc = 0; kc < KH; kc += KCHUNK) {
                __syncthreads();
                for (int idx = tid; idx < BC * (KCHUNK / 4); idx += NTHREADS) {
                    int r = idx >> 5;
                    int j = idx & 31;
                    ((float4*)sH)[r * (KCHUNK / 4) + j] =
                        hsrc[r * (KH / 4) + (kc >> 2) + j];
                }
                __syncthreads();
#pragma unroll 4
                for (int q = 0; q < KCHUNK / 4; q++) {
                    float4 hv[4], wv[4];
#pragma unroll
                    for (int r = 0; r < 4; r++)
                        hv[r] = *(const float4*)&sH[(row0 + r) * KCHUNK + q * 4];
#pragma unroll
                    for (int g = 0; g < 4; g++)
                        wv[g] = *(const float4*)&sWhh[(g * HC + tx) * WPAD + kc + q * 4];
#pragma unroll
                    for (int r = 0; r < 4; r++)
#pragma unroll
                        for (int g = 0; g < 4; g++)
                            acc[r][g] += hv[r].x * wv[g].x + hv[r].y * wv[g].y +
                                         hv[r].z * wv[g].z + hv[r].w * wv[g].w;
                }
            }
        }

        // elementwise LSTM cell + write h_t
        float* hdst = g_hs + (size_t)t * BB * KH;
#pragma unroll
        for (int r = 0; r < 4; r++) {
            float ig = sigmoidf_(acc[r][0]);
            float fg = sigmoidf_(acc[r][1]);
            float gg = tanhf(acc[r][2]);
            float og = sigmoidf_(acc[r][3]);
            float c = fg * c_reg[r] + ig * gg;
            c_reg[r] = c;
            float h = og * tanhf(c);
            hdst[(size_t)(batch_base + row0 + r) * KH + hid_base + tx] = h;
        }

        grid_sync_all();
    }
}

// ---------------------------------------------------------------------------
// Output projection: out[b,t,:] = hs[t,b,:] @ V_w^T + V_b
// Each block handles 64 linear rows (row = t*B + b) in 4 chunks of 16.
// ---------------------------------------------------------------------------
#define PROJ_ROWS 64
#define PROJ_CHUNK 16
#define VPAD 68

__global__ void __launch_bounds__(NTHREADS, 1)
proj_kernel(const float* __restrict__ V_w,   // [64, 512]
            const float* __restrict__ V_b,   // [64]
            float* __restrict__ out)         // [B, T, 64]
{
    extern __shared__ float smem[];
    float* sV  = smem;                 // [512][VPAD]  transposed: sV[k][m]
    float* sHr = sV + KH * VPAD;       // [16][512]
    float* sVb = sHr + PROJ_CHUNK * KH;// [64]

    const int tid = threadIdx.x;
    const int mg = tid & 15;   // m group: handles m = mg*4 .. mg*4+3
    const int rs = tid >> 4;   // row slot within a 16-row chunk

    for (int idx = tid; idx < MM * KH; idx += NTHREADS) {
        int m = idx >> 9;
        int k = idx & 511;
        sV[k * VPAD + m] = V_w[idx];
    }
    for (int idx = tid; idx < MM; idx += NTHREADS) sVb[idx] = V_b[idx];
    __syncthreads();

    const int row_base = blockIdx.x * PROJ_ROWS;

    for (int ch = 0; ch < PROJ_ROWS; ch += PROJ_CHUNK) {
        // load 16 rows of hs (coalesced float4)
        const float4* src = (const float4*)(g_hs + (size_t)(row_base + ch) * KH);
        for (int idx = tid; idx < PROJ_CHUNK * (KH / 4); idx += NTHREADS) {
            ((float4*)sHr)[idx] = src[idx];
        }
        __syncthreads();

        float acc0 = sVb[mg * 4 + 0];
        float acc1 = sVb[mg * 4 + 1];
        float acc2 = sVb[mg * 4 + 2];
        float acc3 = sVb[mg * 4 + 3];
#pragma unroll 4
        for (int q = 0; q < KH / 4; q++) {
            float4 hv = *(const float4*)&sHr[rs * KH + q * 4];
            float4 v0 = *(const float4*)&sV[(q * 4 + 0) * VPAD + mg * 4];
            float4 v1 = *(const float4*)&sV[(q * 4 + 1) * VPAD + mg * 4];
            float4 v2 = *(const float4*)&sV[(q * 4 + 2) * VPAD + mg * 4];
            float4 v3 = *(const float4*)&sV[(q * 4 + 3) * VPAD + mg * 4];
            acc0 += hv.x * v0.x + hv.y * v1.x + hv.z * v2.x + hv.w * v3.x;
            acc1 += hv.x * v0.y + hv.y * v1.y + hv.z * v2.y + hv.w * v3.y;
            acc2 += hv.x * v0.z + hv.y * v1.z + hv.z * v2.z + hv.w * v3.z;
            acc3 += hv.x * v0.w + hv.y * v1.w + hv.z * v2.w + hv.w * v3.w;
        }

        int row = row_base + ch + rs;     // linear = t*B + b
        int t = row >> 8;                 // / 256
        int b = row & 255;
        float4 o = make_float4(acc0, acc1, acc2, acc3);
        *(float4*)&out[((size_t)b * TT + t) * MM + mg * 4] = o;
        __syncthreads();
    }
}

extern "C" void kernel_launch(void* const* d_in, const int* in_sizes, int n_in,
                              void* d_out, int out_size) {
    const float* inputs = (const float*)d_in[0];
    const float* W_ih   = (const float*)d_in[1];
    const float* W_hh   = (const float*)d_in[2];
    const float* b_ih   = (const float*)d_in[3];
    const float* b_hh   = (const float*)d_in[4];
    const float* V_w    = (const float*)d_in[5];
    const float* V_b    = (const float*)d_in[6];
    float* out = (float*)d_out;

    const int smem1 =
        (GATES * HC * WPAD + GATES * HC * XPAD + 64 + BC * XPAD + BC * KCHUNK) *
        (int)sizeof(float);  // 199,936 B
    const int smem2 = (KH * VPAD + PROJ_CHUNK * KH + 64) * (int)sizeof(float); // 172,288 B

    cudaFuncSetAttribute(lstm_persistent,
                         cudaFuncAttributeMaxDynamicSharedMemorySize, smem1);
    cudaFuncSetAttribute(proj_kernel,
                         cudaFuncAttributeMaxDynamicSharedMemorySize, smem2);

    lstm_persistent<<<NCTA, NTHREADS, smem1>>>(inputs, W_ih, W_hh, b_ih, b_hh);
    proj_kernel<<<(BB * TT) / PROJ_ROWS, NTHREADS, smem2>>>(V_w, V_b, out);
}

// round 3
// speedup vs baseline: 1.6442x; 1.6442x over previous
#include <cuda_runtime.h>
#include <math.h>
#include <stdint.h>

#define BB 256
#define TT 1024
#define MM 64
#define KH 512

#define RTHREADS 128
#define NCTA_R 128
#define GRP_CTAS 32

#define APITCH 76
#define BPITCH 644
#define EPITCH 68

// float-offsets into dynamic SMEM
#define OFF_B 0
#define OFF_A0 (64 * BPITCH)                 // 41216
#define OFF_A1 (OFF_A0 + 64 * APITCH)        // 46080
#define OFF_BIAS (OFF_A1 + 64 * APITCH)      // 50944
#define SMEM_FLOATS (OFF_BIAS + 64)
#define SMEM_BYTES (SMEM_FLOATS * 4)         // 204032

__device__ float g_hs[(size_t)TT * BB * KH];
__device__ unsigned g_cnt[4] = {0, 0, 0, 0};
__device__ unsigned g_gen[4] = {0, 0, 0, 0};

__device__ __forceinline__ uint32_t f2tf32(float x) {
    uint32_t r;
    asm("cvt.rna.tf32.f32 %0, %1;" : "=r"(r) : "f"(x));
    return r;
}

// One K-chunk of the gate GEMM. As: [64][APITCH] (rows=batch), Bk: weight
// rows [64][BPITCH] offset to this chunk's K columns. Warp tile 32x32.
template <int NKS>
__device__ __forceinline__ void compute_chunk(const float* __restrict__ As,
                                              const float* __restrict__ Bk,
                                              int m0w, int n0w, int gid, int tig,
                                              float (&d)[2][4][4]) {
#pragma unroll
    for (int ks = 0; ks < NKS; ks++) {
        const int k0 = ks * 8;
        uint32_t a[2][4];
#pragma unroll
        for (int mt = 0; mt < 2; mt++) {
            const float* ap = As + (m0w + mt * 16 + gid) * APITCH + k0 + tig;
            a[mt][0] = __float_as_uint(ap[0]);
            a[mt][1] = __float_as_uint(ap[8 * APITCH]);
            a[mt][2] = __float_as_uint(ap[4]);
            a[mt][3] = __float_as_uint(ap[8 * APITCH + 4]);
        }
        uint32_t b[4][2];
#pragma unroll
        for (int nt = 0; nt < 4; nt++) {
            const float* bp = Bk + (n0w + nt * 8 + gid) * BPITCH + k0 + tig;
            b[nt][0] = __float_as_uint(bp[0]);
            b[nt][1] = __float_as_uint(bp[4]);
        }
#pragma unroll
        for (int mt = 0; mt < 2; mt++)
#pragma unroll
            for (int nt = 0; nt < 4; nt++)
                asm volatile(
                    "mma.sync.aligned.m16n8k8.row.col.f32.tf32.tf32.f32 "
                    "{%0,%1,%2,%3}, {%4,%5,%6,%7}, {%8,%9}, {%0,%1,%2,%3};"
                    : "+f"(d[mt][nt][0]), "+f"(d[mt][nt][1]),
                      "+f"(d[mt][nt][2]), "+f"(d[mt][nt][3])
                    : "r"(a[mt][0]), "r"(a[mt][1]), "r"(a[mt][2]), "r"(a[mt][3]),
                      "r"(b[nt][0]), "r"(b[nt][1]));
    }
}

__device__ __forceinline__ float fast_sigmoid(float x) {
    return 1.0f / (1.0f + __expf(-x));
}
__device__ __forceinline__ float fast_tanh(float x) {
    x = fminf(fmaxf(x, -9.0f), 9.0f);
    float e2 = __expf(2.0f * x);
    return (e2 - 1.0f) / (e2 + 1.0f);
}

// ---------------------------------------------------------------------------
// Persistent tf32 mma.sync LSTM recurrence.
// CTA (grp,hj): batch rows [grp*64,+64), hidden units [hj*16,+16) x 4 gates.
// Gate col r = u*4+g. Barrier is per-batch-group (32 CTAs each).
// ---------------------------------------------------------------------------
__global__ void __launch_bounds__(RTHREADS, 1)
lstm_mma(const float* __restrict__ inputs, const float* __restrict__ W_ih,
         const float* __restrict__ W_hh, const float* __restrict__ b_ih,
         const float* __restrict__ b_hh) {
    extern __shared__ __align__(16) float sm[];
    float* Bw = sm + OFF_B;
    float* A0 = sm + OFF_A0;
    float* A1 = sm + OFF_A1;
    float* sBias = sm + OFF_BIAS;

    const int tid = threadIdx.x;
    const int wid = tid >> 5;
    const int lane = tid & 31;
    const int gid = lane >> 2, tig = lane & 3;
    const int m0w = (wid >> 1) * 32, n0w = (wid & 1) * 32;

    const int grp = blockIdx.x >> 5;      // batch tile 0..3
    const int hj = blockIdx.x & 31;       // hidden tile 0..31
    const int batch_base = grp * 64;
    const int hid_base = hj * 16;

    // ---- one-time: weights (tf32-rounded) + bias ----
    for (int idx = tid; idx < 64 * BPITCH; idx += RTHREADS) {
        int r = idx / BPITCH, k = idx - r * BPITCH;
        int u = r >> 2, g = r & 3;
        int grow = g * KH + hid_base + u;
        float w = 0.0f;
        if (k < KH) w = W_hh[(size_t)grow * KH + k];
        else if (k < KH + 65) w = W_ih[(size_t)grow * 65 + (k - KH)];
        Bw[idx] = __uint_as_float(f2tf32(w));
    }
    for (int idx = tid; idx < 64; idx += RTHREADS) {
        int u = idx >> 2, g = idx & 3;
        int grow = g * KH + hid_base + u;
        sBias[idx] = b_ih[grow] + b_hh[grow];
    }
    __syncthreads();

    // replay-safe barrier base
    unsigned gen_base = 0;
    if (tid == 0) gen_base = atomicAdd(&g_gen[grp], 0u);
    gen_base = __shfl_sync(0xFFFFFFFF, gen_base, 0);

    float c_state[8];
#pragma unroll
    for (int i = 0; i < 8; i++) c_state[i] = 0.0f;

    for (int t = 0; t < TT; ++t) {
        float d[2][4][4];
#pragma unroll
        for (int mt = 0; mt < 2; mt++)
#pragma unroll
            for (int nt = 0; nt < 4; nt++)
#pragma unroll
                for (int i = 0; i < 4; i++) d[mt][nt][i] = 0.0f;

        // ---- x chunk first (independent of barrier) -> A0 ----
        {
            const float* xs = inputs + (size_t)batch_base * (TT * 65) + (size_t)t * 65;
            for (int idx = tid; idx < 64 * 72; idx += RTHREADS) {
                int m = idx / 72, j = idx - m * 72;
                float v = (j < 65) ? xs[(size_t)m * (TT * 65) + j] : 0.0f;
                A0[m * APITCH + j] = __uint_as_float(f2tf32(v));
            }
        }
        __syncthreads();
        compute_chunk<9>(A0, Bw + KH, m0w, n0w, gid, tig, d);

        // ---- wait for h(t-1), then 8 h chunks (double-buffered) ----
        if (t > 0) {
            if (tid == 0) {
                unsigned target = gen_base + (unsigned)t;
                while (atomicAdd(&g_gen[grp], 0u) < target) __nanosleep(32);
                __threadfence();
            }
            __syncthreads();

            const float4* src = (const float4*)(g_hs + (size_t)(t - 1) * BB * KH +
                                                (size_t)batch_base * KH);
#pragma unroll 1
            for (int j = 0; j < 8; j++) {
                float* Ab = (j & 1) ? A0 : A1;   // j=0 -> A1, ..., j=7 -> A0
#pragma unroll
                for (int i = 0; i < 8; i++) {
                    int idx = tid + i * RTHREADS;
                    int m = idx >> 4, q = idx & 15;
                    float4 v = src[(size_t)m * (KH / 4) + j * 16 + q];
                    *(float4*)&Ab[m * APITCH + q * 4] = v;
                }
                __syncthreads();
                compute_chunk<8>(Ab, Bw + j * 64, m0w, n0w, gid, tig, d);
            }
        }

        // ---- epilogue: fragments -> SMEM (A1 region) -> cell -> h store ----
        float* Ep = A1;
#pragma unroll
        for (int mt = 0; mt < 2; mt++)
#pragma unroll
            for (int nt = 0; nt < 4; nt++) {
                int rrow = m0w + mt * 16 + gid;
                int col = n0w + nt * 8 + tig * 2;
                Ep[rrow * EPITCH + col] = d[mt][nt][0];
                Ep[rrow * EPITCH + col + 1] = d[mt][nt][1];
                Ep[(rrow + 8) * EPITCH + col] = d[mt][nt][2];
                Ep[(rrow + 8) * EPITCH + col + 1] = d[mt][nt][3];
            }
        __syncthreads();

        float* hdst = g_hs + (size_t)t * BB * KH + (size_t)batch_base * KH + hid_base;
#pragma unroll
        for (int i = 0; i < 8; i++) {
            int idx = tid + i * RTHREADS;
            int m = idx >> 4, u = idx & 15;
            float4 gt = *(const float4*)&Ep[m * EPITCH + 4 * u];
            float iv = fast_sigmoid(gt.x + sBias[4 * u + 0]);
            float fv = fast_sigmoid(gt.y + sBias[4 * u + 1]);
            float gv = fast_tanh(gt.z + sBias[4 * u + 2]);
            float ov = fast_sigmoid(gt.w + sBias[4 * u + 3]);
            float cc = fv * c_state[i] + iv * gv;
            c_state[i] = cc;
            float hv = ov * fast_tanh(cc);
            hdst[(size_t)m * KH + u] = __uint_as_float(f2tf32(hv));
        }
        __syncthreads();

        if (tid == 0) {
            __threadfence();
            unsigned old = atomicInc(&g_cnt[grp], GRP_CTAS - 1);
            if (old == GRP_CTAS - 1) atomicAdd(&g_gen[grp], 1u);
        }
    }
}

// ---------------------------------------------------------------------------
// Output projection: out[b,t,:] = hs[t,b,:] @ V_w^T + V_b
// ---------------------------------------------------------------------------
#define NTHREADS 256
#define PROJ_ROWS 64
#define PROJ_CHUNK 16
#define VPAD 68

__global__ void __launch_bounds__(NTHREADS, 1)
proj_kernel(const float* __restrict__ V_w, const float* __restrict__ V_b,
            float* __restrict__ out) {
    extern __shared__ __align__(16) float smemf[];
    float* sV = smemf;                    // [512][VPAD]
    float* sHr = sV + KH * VPAD;          // [16][512]
    float* sVb = sHr + PROJ_CHUNK * KH;   // [64]

    const int tid = threadIdx.x;
    const int mg = tid & 15;
    const int rs = tid >> 4;

    for (int idx = tid; idx < MM * KH; idx += NTHREADS) {
        int m = idx >> 9;
        int k = idx & 511;
        sV[k * VPAD + m] = V_w[idx];
    }
    for (int idx = tid; idx < MM; idx += NTHREADS) sVb[idx] = V_b[idx];
    __syncthreads();

    const int row_base = blockIdx.x * PROJ_ROWS;

    for (int ch = 0; ch < PROJ_ROWS; ch += PROJ_CHUNK) {
        const float4* src = (const float4*)(g_hs + (size_t)(row_base + ch) * KH);
        for (int idx = tid; idx < PROJ_CHUNK * (KH / 4); idx += NTHREADS) {
            ((float4*)sHr)[idx] = src[idx];
        }
        __syncthreads();

        float acc0 = sVb[mg * 4 + 0];
        float acc1 = sVb[mg * 4 + 1];
        float acc2 = sVb[mg * 4 + 2];
        float acc3 = sVb[mg * 4 + 3];
#pragma unroll 4
        for (int q = 0; q < KH / 4; q++) {
            float4 hv = *(const float4*)&sHr[rs * KH + q * 4];
            float4 v0 = *(const float4*)&sV[(q * 4 + 0) * VPAD + mg * 4];
            float4 v1 = *(const float4*)&sV[(q * 4 + 1) * VPAD + mg * 4];
            float4 v2 = *(const float4*)&sV[(q * 4 + 2) * VPAD + mg * 4];
            float4 v3 = *(const float4*)&sV[(q * 4 + 3) * VPAD + mg * 4];
            acc0 += hv.x * v0.x + hv.y * v1.x + hv.z * v2.x + hv.w * v3.x;
            acc1 += hv.x * v0.y + hv.y * v1.y + hv.z * v2.y + hv.w * v3.y;
            acc2 += hv.x * v0.z + hv.y * v1.z + hv.z * v2.z + hv.w * v3.z;
            acc3 += hv.x * v0.w + hv.y * v1.w + hv.z * v2.w + hv.w * v3.w;
        }

        int row = row_base + ch + rs;   // linear = t*B + b
        int t = row >> 8;
        int b = row & 255;
        float4 o = make_float4(acc0, acc1, acc2, acc3);
        *(float4*)&out[((size_t)b * TT + t) * MM + mg * 4] = o;
        __syncthreads();
    }
}

extern "C" void kernel_launch(void* const* d_in, const int* in_sizes, int n_in,
                              void* d_out, int out_size) {
    const float* inputs = (const float*)d_in[0];
    const float* W_ih   = (const float*)d_in[1];
    const float* W_hh   = (const float*)d_in[2];
    const float* b_ih   = (const float*)d_in[3];
    const float* b_hh   = (const float*)d_in[4];
    const float* V_w    = (const float*)d_in[5];
    const float* V_b    = (const float*)d_in[6];
    float* out = (float*)d_out;

    const int smem2 = (KH * VPAD + PROJ_CHUNK * KH + 64) * (int)sizeof(float);

    cudaFuncSetAttribute(lstm_mma, cudaFuncAttributeMaxDynamicSharedMemorySize,
                         SMEM_BYTES);
    cudaFuncSetAttribute(proj_kernel, cudaFuncAttributeMaxDynamicSharedMemorySize,
                         smem2);

    lstm_mma<<<NCTA_R, RTHREADS, SMEM_BYTES>>>(inputs, W_ih, W_hh, b_ih, b_hh);
    proj_kernel<<<(BB * TT) / PROJ_ROWS, NTHREADS, smem2>>>(V_w, V_b, out);
}

// round 6
// speedup vs baseline: 2.1621x; 1.3150x over previous
#include <cuda_runtime.h>
#include <math.h>
#include <stdint.h>

#define BB 256
#define TT 1024
#define MM 64
#define KH 512

#define RTHREADS 128
#define NCTA_R 128
#define GRP_CTAS 32

#define APITCH 76
#define BPITCH 644
#define XPITCH 68
#define EPITCH 68

// float-offsets into dynamic SMEM
#define OFF_B 0
#define OFF_A0 (64 * BPITCH)                  // 41216
#define OFF_A1 (OFF_A0 + 64 * APITCH)         // 46080
#define OFF_XR (OFF_A1 + 64 * APITCH)         // 50944
#define OFF_BIAS (OFF_XR + 64 * XPITCH)       // 55296
#define SMEM_FLOATS (OFF_BIAS + 64)
#define SMEM_BYTES (SMEM_FLOATS * 4)          // 221440

__device__ float g_hs[(size_t)TT * BB * KH];
__device__ unsigned g_cnt[4] = {0, 0, 0, 0};
__device__ unsigned g_gen[4] = {0, 0, 0, 0};

__device__ __forceinline__ uint32_t f2tf32(float x) {
    uint32_t r;
    asm("cvt.rna.tf32.f32 %0, %1;" : "=r"(r) : "f"(x));
    return r;
}
__device__ __forceinline__ uint32_t smaddr(const void* p) {
    return (uint32_t)__cvta_generic_to_shared(p);
}

#define CP_COMMIT() asm volatile("cp.async.commit_group;" ::: "memory")
#define CP_WAIT0() asm volatile("cp.async.wait_group 0;" ::: "memory")

// prefetch h chunk j (64 rows x 64 cols) from g_hs into Ab
__device__ __forceinline__ void prefetch_h(const float4* __restrict__ src,
                                           float* Ab, int j, int tid) {
#pragma unroll
    for (int i = 0; i < 8; i++) {
        int idx = tid + i * RTHREADS;
        int m = idx >> 4, q = idx & 15;
        uint32_t dst = smaddr(&Ab[m * APITCH + q * 4]);
        const float4* g = src + (size_t)m * (KH / 4) + j * 16 + q;
        asm volatile("cp.async.cg.shared.global [%0], [%1], 16;"
                     :: "r"(dst), "l"(g) : "memory");
    }
    CP_COMMIT();
}

// prefetch raw x_t tile (64 rows x 65 floats) into XR (4B granules: row base
// offsets are t*260 bytes -> only 4B aligned)
__device__ __forceinline__ void prefetch_x(const float* __restrict__ xs,
                                           float* XR, int tid) {
    for (int idx = tid; idx < 64 * 65; idx += RTHREADS) {
        int m = idx / 65, j = idx - m * 65;
        uint32_t dst = smaddr(&XR[m * XPITCH + j]);
        const float* g = xs + (size_t)m * (TT * 65) + j;
        asm volatile("cp.async.ca.shared.global [%0], [%1], 4;"
                     :: "r"(dst), "l"(g) : "memory");
    }
    CP_COMMIT();
}

// One K-chunk of the gate GEMM. As: [64][APITCH] rows=batch; Bk: weight rows
// [64][BPITCH] offset to this chunk's K columns. Warp tile 32x32.
template <int NKS>
__device__ __forceinline__ void compute_chunk(const float* __restrict__ As,
                                              const float* __restrict__ Bk,
                                              int m0w, int n0w, int gid, int tig,
                                              float (&d)[2][4][4]) {
#pragma unroll
    for (int ks = 0; ks < NKS; ks++) {
        const int k0 = ks * 8;
        uint32_t a[2][4];
#pragma unroll
        for (int mt = 0; mt < 2; mt++) {
            const float* ap = As + (m0w + mt * 16 + gid) * APITCH + k0 + tig;
            a[mt][0] = __float_as_uint(ap[0]);
            a[mt][1] = __float_as_uint(ap[8 * APITCH]);
            a[mt][2] = __float_as_uint(ap[4]);
            a[mt][3] = __float_as_uint(ap[8 * APITCH + 4]);
        }
        uint32_t b[4][2];
#pragma unroll
        for (int nt = 0; nt < 4; nt++) {
            const float* bp = Bk + (n0w + nt * 8 + gid) * BPITCH + k0 + tig;
            b[nt][0] = __float_as_uint(bp[0]);
            b[nt][1] = __float_as_uint(bp[4]);
        }
#pragma unroll
        for (int mt = 0; mt < 2; mt++)
#pragma unroll
            for (int nt = 0; nt < 4; nt++)
                asm volatile(
                    "mma.sync.aligned.m16n8k8.row.col.f32.tf32.tf32.f32 "
                    "{%0,%1,%2,%3}, {%4,%5,%6,%7}, {%8,%9}, {%0,%1,%2,%3};"
                    : "+f"(d[mt][nt][0]), "+f"(d[mt][nt][1]),
                      "+f"(d[mt][nt][2]), "+f"(d[mt][nt][3])
                    : "r"(a[mt][0]), "r"(a[mt][1]), "r"(a[mt][2]), "r"(a[mt][3]),
                      "r"(b[nt][0]), "r"(b[nt][1]));
    }
}

__device__ __forceinline__ float fast_sigmoid(float x) {
    return 1.0f / (1.0f + __expf(-x));
}
__device__ __forceinline__ float fast_tanh(float x) {
    x = fminf(fmaxf(x, -9.0f), 9.0f);
    float e2 = __expf(2.0f * x);
    return (e2 - 1.0f) / (e2 + 1.0f);
}

// ---------------------------------------------------------------------------
// Persistent tf32 mma.sync LSTM recurrence with cp.async pipelining.
// CTA (grp,hj): batch rows [grp*64,+64), hidden units [hj*16,+16) x 4 gates.
// Barrier per 32-CTA batch group. During the chunk loop only h-chunk cp.async
// groups are in flight (x prefetch is committed after the loop), so every
// wait_group 0 is an L2-latency wait only.
// ---------------------------------------------------------------------------
__global__ void __launch_bounds__(RTHREADS, 1)
lstm_mma(const float* __restrict__ inputs, const float* __restrict__ W_ih,
         const float* __restrict__ W_hh, const float* __restrict__ b_ih,
         const float* __restrict__ b_hh) {
    extern __shared__ __align__(16) float sm[];
    float* Bw = sm + OFF_B;
    float* A0 = sm + OFF_A0;
    float* A1 = sm + OFF_A1;
    float* XR = sm + OFF_XR;
    float* sBias = sm + OFF_BIAS;

    const int tid = threadIdx.x;
    const int wid = tid >> 5;
    const int lane = tid & 31;
    const int gid = lane >> 2, tig = lane & 3;
    const int m0w = (wid >> 1) * 32, n0w = (wid & 1) * 32;

    const int grp = blockIdx.x >> 5;
    const int hj = blockIdx.x & 31;
    const int batch_base = grp * 64;
    const int hid_base = hj * 16;

    const float* xbase = inputs + (size_t)batch_base * (TT * 65);

    // ---- one-time: weights (tf32-rounded) + bias ----
    for (int idx = tid; idx < 64 * BPITCH; idx += RTHREADS) {
        int r = idx / BPITCH, k = idx - r * BPITCH;
        int u = r >> 2, g = r & 3;
        int grow = g * KH + hid_base + u;
        float w = 0.0f;
        if (k < KH) w = W_hh[(size_t)grow * KH + k];
        else if (k < KH + 65) w = W_ih[(size_t)grow * 65 + (k - KH)];
        Bw[idx] = __uint_as_float(f2tf32(w));
    }
    for (int idx = tid; idx < 64; idx += RTHREADS) {
        int u = idx >> 2, g = idx & 3;
        int grow = g * KH + hid_base + u;
        sBias[idx] = b_ih[grow] + b_hh[grow];
    }

    // prime x(0)
    prefetch_x(xbase, XR, tid);
    __syncthreads();

    // Safe across graph replays: a group release needs ALL 32 CTAs' arrivals,
    // so g_gen[grp] cannot advance past this read before our first arrival.
    unsigned gen_base = 0;
    if (tid == 0) gen_base = atomicAdd(&g_gen[grp], 0u);
    gen_base = __shfl_sync(0xFFFFFFFF, gen_base, 0);

    float c_state[8];
#pragma unroll
    for (int i = 0; i < 8; i++) c_state[i] = 0.0f;

    for (int t = 0; t < TT; ++t) {
        float d[2][4][4];
#pragma unroll
        for (int mt = 0; mt < 2; mt++)
#pragma unroll
            for (int nt = 0; nt < 4; nt++)
#pragma unroll
                for (int i = 0; i < 4; i++) d[mt][nt][i] = 0.0f;

        // XR(t) arrived (committed at end of step t-1); convert into A0
        CP_WAIT0();
        __syncthreads();
        for (int idx = tid; idx < 64 * 72; idx += RTHREADS) {
            int m = idx / 72, j = idx - m * 72;
            float v = (j < 65) ? XR[m * XPITCH + j] : 0.0f;
            A0[m * APITCH + j] = __uint_as_float(f2tf32(v));
        }
        __syncthreads();

        const float4* src = (const float4*)(g_hs + (size_t)(t - 1) * BB * KH +
                                            (size_t)batch_base * KH);
        if (t > 0) {
            // wait for h(t-1) from the rest of the group
            if (tid == 0) {
                unsigned target = gen_base + (unsigned)t;
                while (atomicAdd(&g_gen[grp], 0u) < target) __nanosleep(32);
                __threadfence();
            }
            __syncthreads();
            prefetch_h(src, A1, 0, tid);   // chunk0 copy overlaps x GEMM
        }

        compute_chunk<9>(A0, Bw + KH, m0w, n0w, gid, tig, d);

        if (t > 0) {
#pragma unroll 1
            for (int j = 0; j < 8; j++) {
                CP_WAIT0();
                __syncthreads();
                if (j < 7)
                    prefetch_h(src, (j & 1) ? A1 : A0, j + 1, tid);
                compute_chunk<8>((j & 1) ? A0 : A1, Bw + j * 64, m0w, n0w, gid,
                                 tig, d);
            }
        }

        // x(t+1) prefetch: committed AFTER all chunk groups so chunk waits in
        // the next loop never block on DRAM; waited at top of step t+1.
        if (t + 1 < TT) prefetch_x(xbase + (size_t)(t + 1) * 65, XR, tid);

        // ---- epilogue: fragments -> SMEM (A1) -> cell -> h store ----
        float* Ep = A1;
#pragma unroll
        for (int mt = 0; mt < 2; mt++)
#pragma unroll
            for (int nt = 0; nt < 4; nt++) {
                int rrow = m0w + mt * 16 + gid;
                int col = n0w + nt * 8 + tig * 2;
                Ep[rrow * EPITCH + col] = d[mt][nt][0];
                Ep[rrow * EPITCH + col + 1] = d[mt][nt][1];
                Ep[(rrow + 8) * EPITCH + col] = d[mt][nt][2];
                Ep[(rrow + 8) * EPITCH + col + 1] = d[mt][nt][3];
            }
        __syncthreads();

        float* hdst = g_hs + (size_t)t * BB * KH + (size_t)batch_base * KH + hid_base;
#pragma unroll
        for (int i = 0; i < 8; i++) {
            int idx = tid + i * RTHREADS;
            int m = idx >> 4, u = idx & 15;
            float4 gt = *(const float4*)&Ep[m * EPITCH + 4 * u];
            float iv = fast_sigmoid(gt.x + sBias[4 * u + 0]);
            float fv = fast_sigmoid(gt.y + sBias[4 * u + 1]);
            float gv = fast_tanh(gt.z + sBias[4 * u + 2]);
            float ov = fast_sigmoid(gt.w + sBias[4 * u + 3]);
            float cc = fv * c_state[i] + iv * gv;
            c_state[i] = cc;
            float hv = ov * fast_tanh(cc);
            hdst[(size_t)m * KH + u] = __uint_as_float(f2tf32(hv));
        }
        __syncthreads();

        if (tid == 0) {
            __threadfence();
            unsigned old = atomicInc(&g_cnt[grp], GRP_CTAS - 1);
            if (old == GRP_CTAS - 1) atomicAdd(&g_gen[grp], 1u);
        }
    }
}

// ---------------------------------------------------------------------------
// Output projection: out[b,t,:] = hs[t,b,:] @ V_w^T + V_b
// ---------------------------------------------------------------------------
#define NTHREADS 256
#define PROJ_ROWS 64
#define PROJ_CHUNK 16
#define VPAD 68

__global__ void __launch_bounds__(NTHREADS, 1)
proj_kernel(const float* __restrict__ V_w, const float* __restrict__ V_b,
            float* __restrict__ out) {
    extern __shared__ __align__(16) float smemf[];
    float* sV = smemf;                    // [512][VPAD]
    float* sHr = sV + KH * VPAD;          // [16][512]
    float* sVb = sHr + PROJ_CHUNK * KH;   // [64]

    const int tid = threadIdx.x;
    const int mg = tid & 15;
    const int rs = tid >> 4;

    for (int idx = tid; idx < MM * KH; idx += NTHREADS) {
        int m = idx >> 9;
        int k = idx & 511;
        sV[k * VPAD + m] = V_w[idx];
    }
    for (int idx = tid; idx < MM; idx += NTHREADS) sVb[idx] = V_b[idx];
    __syncthreads();

    const int row_base = blockIdx.x * PROJ_ROWS;

    for (int ch = 0; ch < PROJ_ROWS; ch += PROJ_CHUNK) {
        const float4* src = (const float4*)(g_hs + (size_t)(row_base + ch) * KH);
        for (int idx = tid; idx < PROJ_CHUNK * (KH / 4); idx += NTHREADS) {
            ((float4*)sHr)[idx] = src[idx];
        }
        __syncthreads();

        float acc0 = sVb[mg * 4 + 0];
        float acc1 = sVb[mg * 4 + 1];
        float acc2 = sVb[mg * 4 + 2];
        float acc3 = sVb[mg * 4 + 3];
#pragma unroll 4
        for (int q = 0; q < KH / 4; q++) {
            float4 hv = *(const float4*)&sHr[rs * KH + q * 4];
            float4 v0 = *(const float4*)&sV[(q * 4 + 0) * VPAD + mg * 4];
            float4 v1 = *(const float4*)&sV[(q * 4 + 1) * VPAD + mg * 4];
            float4 v2 = *(const float4*)&sV[(q * 4 + 2) * VPAD + mg * 4];
            float4 v3 = *(const float4*)&sV[(q * 4 + 3) * VPAD + mg * 4];
            acc0 += hv.x * v0.x + hv.y * v1.x + hv.z * v2.x + hv.w * v3.x;
            acc1 += hv.x * v0.y + hv.y * v1.y + hv.z * v2.y + hv.w * v3.y;
            acc2 += hv.x * v0.z + hv.y * v1.z + hv.z * v2.z + hv.w * v3.z;
            acc3 += hv.x * v0.w + hv.y * v1.w + hv.z * v2.w + hv.w * v3.w;
        }

        int row = row_base + ch + rs;   // linear = t*B + b
        int t = row >> 8;
        int b = row & 255;
        float4 o = make_float4(acc0, acc1, acc2, acc3);
        *(float4*)&out[((size_t)b * TT + t) * MM + mg * 4] = o;
        __syncthreads();
    }
}

extern "C" void kernel_launch(void* const* d_in, const int* in_sizes, int n_in,
                              void* d_out, int out_size) {
    const float* inputs = (const float*)d_in[0];
    const float* W_ih   = (const float*)d_in[1];
    const float* W_hh   = (const float*)d_in[2];
    const float* b_ih   = (const float*)d_in[3];
    const float* b_hh   = (const float*)d_in[4];
    const float* V_w    = (const float*)d_in[5];
    const float* V_b    = (const float*)d_in[6];
    float* out = (float*)d_out;

    const int smem2 = (KH * VPAD + PROJ_CHUNK * KH + 64) * (int)sizeof(float);

    cudaFuncSetAttribute(lstm_mma, cudaFuncAttributeMaxDynamicSharedMemorySize,
                         SMEM_BYTES);
    cudaFuncSetAttribute(proj_kernel, cudaFuncAttributeMaxDynamicSharedMemorySize,
                         smem2);

    lstm_mma<<<NCTA_R, RTHREADS, SMEM_BYTES>>>(inputs, W_ih, W_hh, b_ih, b_hh);
    proj_kernel<<<(BB * TT) / PROJ_ROWS, NTHREADS, smem2>>>(V_w, V_b, out);
}